// round 2
// baseline (speedup 1.0000x reference)
#include <cuda_runtime.h>
#include <cstdint>

namespace {
constexpr int NS   = 512;
constexpr int MPTS = 8192;
constexpr int HW   = 16384;
constexpr int HW4  = 4096;

constexpr int PV_CH_PER_S = 16;    // 1024 px per chunk
constexpr int PV_F4_PER_CH = 256;  // float4 per chunk
constexpr int NPV = NS * PV_CH_PER_S;       // 8192
constexpr int MS_CH_PER_S = 8;     // 1024 points per chunk
constexpr int MS_PT_PER_CH = 1024;
constexpr int NMS = NS * MS_CH_PER_S;       // 4096
constexpr unsigned NCHUNK = NPV + NMS;      // 12288

constexpr int GRID  = 740;   // 148 SMs x 5 (work stealing tolerates occupancy drop)
constexpr int BLOCK = 256;
}

__device__ unsigned g_ctr;
__device__ unsigned g_done;
__device__ int      g_mask_mode;   // 0=f32, 1=i32, 2=packed u8
__device__ float2   g_pv[NPV];
__device__ float2   g_pj[NMS];

__device__ __forceinline__ float frcp(float x)  { float r; asm("rcp.approx.f32 %0,%1;"  : "=f"(r) : "f"(x)); return r; }
__device__ __forceinline__ float fsqrt(float x) { float r; asm("sqrt.approx.f32 %0,%1;" : "=f"(r) : "f"(x)); return r; }

// Reset counters + classify mask dtype from bit patterns of first 1KB.
__global__ void init_kernel(const unsigned* __restrict__ mw) {
    unsigned f = 0, o = 0;
    for (int i = threadIdx.x; i < 256; i += 32) {
        unsigned w = mw[i];
        if (w == 0x3F800000u) f = 1;
        else if (w != 0u && w != 1u) o = 1;
    }
    f = __any_sync(0xFFFFFFFFu, f);
    o = __any_sync(0xFFFFFFFFu, o);
    if (threadIdx.x == 0) {
        g_mask_mode = f ? 0 : (o ? 2 : 1);
        g_ctr  = 0u;
        g_done = 0u;
    }
}

__global__ void __launch_bounds__(BLOCK, 4) score_kernel(
    const int*   __restrict__ obj_id,
    const float* __restrict__ camK,
    const float* __restrict__ Rg_all,
    const float* __restrict__ tg_all,
    const float* __restrict__ Rp_all,
    const float* __restrict__ tp_all,
    const float* __restrict__ coord,
    const void*  __restrict__ mask,
    const float* __restrict__ mesh,
    const float* __restrict__ diam,
    float*       __restrict__ out)    // [5*NS]: re|te|ad|pj|pv
{
    const int lane = threadIdx.x & 31;
    const int mode = g_mask_mode;

    unsigned cur = 0;
    if (lane == 0) cur = atomicAdd(&g_ctr, 1u);
    cur = __shfl_sync(0xFFFFFFFFu, cur, 0);

    while (cur < NCHUNK) {
        unsigned nxt = 0;
        if (lane == 0) nxt = atomicAdd(&g_ctr, 1u);   // prefetch next chunk id
        nxt = __shfl_sync(0xFFFFFFFFu, nxt, 0);

        if (cur < (unsigned)NPV) {
            // ================= PV chunk: 1024 ROI pixels =================
            const int n = (int)(cur >> 4), part = (int)(cur & 15);
            float Rp[9], Rg[9];
#pragma unroll
            for (int i = 0; i < 9; i++) {
                Rp[i] = __ldg(Rp_all + n * 9 + i);
                Rg[i] = __ldg(Rg_all + n * 9 + i);
            }
            const float tp0 = __ldg(tp_all + n*3+0), tp1 = __ldg(tp_all + n*3+1), tp2 = __ldg(tp_all + n*3+2);
            const float tg0 = __ldg(tg_all + n*3+0), tg1 = __ldg(tg_all + n*3+1), tg2 = __ldg(tg_all + n*3+2);
            const float fx = __ldg(camK + n*9 + 0), fy = __ldg(camK + n*9 + 4);

            const float4* x4 = (const float4*)coord + (size_t)n * 3 * HW4 + part * PV_F4_PER_CH;
            float sum = 0.f, cnt = 0.f;

#pragma unroll 2
            for (int it = 0; it < 8; ++it) {
                const int f = it * 32 + lane;
                float4 X = x4[f], Y = x4[f + HW4], Z = x4[f + 2 * HW4];
                float mv[4];
                const size_t mi = (size_t)n * HW4 + part * PV_F4_PER_CH + f;
                if (mode == 0) {
                    float4 M = ((const float4*)mask)[mi];
                    mv[0] = M.x; mv[1] = M.y; mv[2] = M.z; mv[3] = M.w;
                } else if (mode == 1) {
                    int4 M = ((const int4*)mask)[mi];
                    mv[0] = (float)M.x; mv[1] = (float)M.y; mv[2] = (float)M.z; mv[3] = (float)M.w;
                } else {
                    unsigned w = ((const unsigned*)mask)[mi];
                    mv[0] = (float)(w & 255u); mv[1] = (float)((w >> 8) & 255u);
                    mv[2] = (float)((w >> 16) & 255u); mv[3] = (float)(w >> 24);
                }
                const float xs[4] = {X.x, X.y, X.z, X.w};
                const float ys[4] = {Y.x, Y.y, Y.z, Y.w};
                const float zs[4] = {Z.x, Z.y, Z.z, Z.w};
#pragma unroll
                for (int k = 0; k < 4; k++) {
                    const float v0 = xs[k], v1 = ys[k], v2 = zs[k];
                    float p0 = fmaf(Rp[0], v0, fmaf(Rp[1], v1, fmaf(Rp[2], v2, tp0)));
                    float p1 = fmaf(Rp[3], v0, fmaf(Rp[4], v1, fmaf(Rp[5], v2, tp1)));
                    float p2 = fmaf(Rp[6], v0, fmaf(Rp[7], v1, fmaf(Rp[8], v2, tp2)));
                    float g0 = fmaf(Rg[0], v0, fmaf(Rg[1], v1, fmaf(Rg[2], v2, tg0)));
                    float g1 = fmaf(Rg[3], v0, fmaf(Rg[4], v1, fmaf(Rg[5], v2, tg1)));
                    float g2 = fmaf(Rg[6], v0, fmaf(Rg[7], v1, fmaf(Rg[8], v2, tg2)));
                    // p0/p2 - g0/g2 = (p0*g2 - g0*p2) / (p2*g2): single rcp
                    float t0 = fmaf(p0, g2, -(g0 * p2));
                    float t1 = fmaf(p1, g2, -(g1 * p2));
                    float r  = frcp(p2 * g2);
                    float du = fx * (t0 * r);
                    float dv = fy * (t1 * r);
                    float d  = fsqrt(fmaf(du, du, dv * dv));
                    sum = fmaf(d, mv[k], sum);
                    cnt += mv[k];
                }
            }
#pragma unroll
            for (int o = 16; o; o >>= 1) {
                sum += __shfl_down_sync(0xFFFFFFFFu, sum, o);
                cnt += __shfl_down_sync(0xFFFFFFFFu, cnt, o);
            }
            if (lane == 0) g_pv[cur] = make_float2(sum, cnt);
        } else {
            // ================= MESH chunk: 1024 points =================
            const int c2 = (int)(cur - NPV);
            const int n = c2 >> 3, part = c2 & 7;
            const int obj = __ldg(obj_id + n);
            float Rg[9], dR[9];
#pragma unroll
            for (int i = 0; i < 9; i++) {
                Rg[i] = __ldg(Rg_all + n * 9 + i);
                dR[i] = __ldg(Rp_all + n * 9 + i) - Rg[i];
            }
            const float tg0 = __ldg(tg_all + n*3+0), tg1 = __ldg(tg_all + n*3+1), tg2 = __ldg(tg_all + n*3+2);
            const float dt0 = __ldg(tp_all + n*3+0) - tg0;
            const float dt1 = __ldg(tp_all + n*3+1) - tg1;
            const float dt2 = __ldg(tp_all + n*3+2) - tg2;
            const float fx = __ldg(camK + n*9 + 0), fy = __ldg(camK + n*9 + 4);
            const float* mp = mesh + (size_t)obj * MPTS * 3 + (size_t)part * MS_PT_PER_CH * 3;

            float adsum = 0.f, pjsum = 0.f;
#pragma unroll 4
            for (int it = 0; it < 32; ++it) {
                const int m = it * 32 + lane;
                const float v0 = __ldg(mp + m * 3 + 0);
                const float v1 = __ldg(mp + m * 3 + 1);
                const float v2 = __ldg(mp + m * 3 + 2);
                float e0 = fmaf(dR[0], v0, fmaf(dR[1], v1, fmaf(dR[2], v2, dt0)));
                float e1 = fmaf(dR[3], v0, fmaf(dR[4], v1, fmaf(dR[5], v2, dt1)));
                float e2 = fmaf(dR[6], v0, fmaf(dR[7], v1, fmaf(dR[8], v2, dt2)));
                float g0 = fmaf(Rg[0], v0, fmaf(Rg[1], v1, fmaf(Rg[2], v2, tg0)));
                float g1 = fmaf(Rg[3], v0, fmaf(Rg[4], v1, fmaf(Rg[5], v2, tg1)));
                float g2 = fmaf(Rg[6], v0, fmaf(Rg[7], v1, fmaf(Rg[8], v2, tg2)));
                adsum += fsqrt(fmaf(e0, e0, fmaf(e1, e1, e2 * e2)));
                // p = g + e;  p0/p2 - g0/g2 = (e0*g2 - g0*e2)/(p2*g2)
                float t0 = fmaf(e0, g2, -(g0 * e2));
                float t1 = fmaf(e1, g2, -(g1 * e2));
                float p2 = g2 + e2;
                float r  = frcp(p2 * g2);
                float du = fx * (t0 * r);
                float dv = fy * (t1 * r);
                pjsum += fsqrt(fmaf(du, du, dv * dv));
            }
#pragma unroll
            for (int o = 16; o; o >>= 1) {
                adsum += __shfl_down_sync(0xFFFFFFFFu, adsum, o);
                pjsum += __shfl_down_sync(0xFFFFFFFFu, pjsum, o);
            }
            if (lane == 0) {
                g_pj[c2] = make_float2(adsum, pjsum);
                if (part == 0) {
                    // RE: trace(Rp Rg^T) = sum (Rg+dR) .* Rg
                    float tr = 0.f;
#pragma unroll
                    for (int i = 0; i < 9; i++) tr = fmaf(dR[i] + Rg[i], Rg[i], tr);
                    tr = fminf(fmaxf(tr, -1.0f), 3.0f);
                    out[n] = acosf((tr - 1.0f) * 0.5f) * 57.29577951308232f;
                    out[NS + n] = sqrtf(fmaf(dt0, dt0, fmaf(dt1, dt1, dt2 * dt2))) * 100.0f;
                }
            }
        }
        cur = nxt;
    }

    // ---- last block assembles per-sample results from scratch ----
    __syncthreads();
    __shared__ bool amLast;
    if (threadIdx.x == 0) {
        __threadfence();
        amLast = (atomicAdd(&g_done, 1u) == (unsigned)(GRID - 1));
    }
    __syncthreads();
    if (amLast) {
        for (int s = threadIdx.x; s < NS; s += BLOCK) {
            float sum = 0.f, cnt = 0.f;
#pragma unroll
            for (int k = 0; k < PV_CH_PER_S; k++) {
                float2 v = __ldcg(&g_pv[s * PV_CH_PER_S + k]);
                sum += v.x; cnt += v.y;
            }
            out[4 * NS + s] = sum / fmaxf(cnt, 1.0f);
            float ad = 0.f, pj = 0.f;
#pragma unroll
            for (int k = 0; k < MS_CH_PER_S; k++) {
                float2 v = __ldcg(&g_pj[s * MS_CH_PER_S + k]);
                ad += v.x; pj += v.y;
            }
            const int ob = __ldg(obj_id + s);
            out[2 * NS + s] = ad * (1.0f / MPTS) / __ldg(diam + ob);
            out[3 * NS + s] = pj * (1.0f / MPTS);
        }
    }
}

extern "C" void kernel_launch(void* const* d_in, const int* in_sizes, int n_in,
                              void* d_out, int out_size) {
    (void)in_sizes; (void)n_in; (void)out_size;
    const int*   obj_id = (const int*)  d_in[0];
    const float* camK   = (const float*)d_in[1];
    const float* gtR    = (const float*)d_in[2];
    const float* gtT    = (const float*)d_in[3];
    const float* prR    = (const float*)d_in[4];
    const float* prT    = (const float*)d_in[5];
    const float* coord  = (const float*)d_in[6];
    const void*  mask   =               d_in[7];
    const float* mesh   = (const float*)d_in[8];
    const float* diam   = (const float*)d_in[9];
    float* out = (float*)d_out;

    init_kernel<<<1, 32>>>((const unsigned*)mask);
    score_kernel<<<GRID, BLOCK>>>(obj_id, camK, gtR, gtT, prR, prT,
                                  coord, mask, mesh, diam, out);
}

// round 3
// speedup vs baseline: 1.2043x; 1.2043x over previous
#include <cuda_runtime.h>
#include <cstdint>

namespace {
constexpr int NS   = 512;
constexpr int MPTS = 8192;
constexpr int HW4  = 4096;        // float4 words per HxW plane
constexpr int GRID  = 2 * NS;     // 1024 blocks, one half-sample each
constexpr int BLOCK = 128;
constexpr int PV_F4 = HW4 / 2;    // 2048 float4 per half (8192 px)
constexpr int MS_PT = MPTS / 2;   // 4096 mesh pts per half
}

__device__ int    g_mask_mode;       // 0=f32, 1=i32, 2=packed u8
__device__ unsigned g_flag[NS];
__device__ float4 g_part[GRID];      // (pvsum, pvcnt, adsum, pjsum)

__device__ __forceinline__ float frcp(float x)  { float r; asm("rcp.approx.f32 %0,%1;"  : "=f"(r) : "f"(x)); return r; }
__device__ __forceinline__ float fsqrt(float x) { float r; asm("sqrt.approx.f32 %0,%1;" : "=f"(r) : "f"(x)); return r; }

__global__ void init_kernel(const unsigned* __restrict__ mw) {
    unsigned f = 0, o = 0;
    for (int i = threadIdx.x; i < 256; i += 32) {
        unsigned w = mw[i];
        if (w == 0x3F800000u) f = 1;
        else if (w != 0u && w != 1u) o = 1;
    }
    f = __any_sync(0xFFFFFFFFu, f);
    o = __any_sync(0xFFFFFFFFu, o);
    if (threadIdx.x == 0) g_mask_mode = f ? 0 : (o ? 2 : 1);
    for (int i = threadIdx.x; i < NS; i += 32) g_flag[i] = 0u;
}

__global__ void __launch_bounds__(BLOCK, 8) score_kernel(
    const int*   __restrict__ obj_id,
    const float* __restrict__ camK,
    const float* __restrict__ Rg_all,
    const float* __restrict__ tg_all,
    const float* __restrict__ Rp_all,
    const float* __restrict__ tp_all,
    const float* __restrict__ coord,
    const void*  __restrict__ mask,
    const float* __restrict__ mesh,
    const float* __restrict__ diam,
    float*       __restrict__ out)    // [5*NS]: re|te|ad|pj|pv
{
    const int tid  = threadIdx.x;
    const int lane = tid & 31;
    const int wid  = tid >> 5;
    const int b    = blockIdx.x;
    const int n    = b >> 1;
    const int half = b & 1;
    const int mode = g_mask_mode;

    // ---- per-sample constants (broadcast; one L1 line each) ----
    float Rp[9], Rg[9];
#pragma unroll
    for (int i = 0; i < 9; i++) {
        Rp[i] = __ldg(Rp_all + n * 9 + i);
        Rg[i] = __ldg(Rg_all + n * 9 + i);
    }
    const float tp0 = __ldg(tp_all + n*3+0), tp1 = __ldg(tp_all + n*3+1), tp2 = __ldg(tp_all + n*3+2);
    const float tg0 = __ldg(tg_all + n*3+0), tg1 = __ldg(tg_all + n*3+1), tg2 = __ldg(tg_all + n*3+2);
    const float fx  = __ldg(camK + n*9 + 0), fy = __ldg(camK + n*9 + 4);

    __shared__ float sred[4][4];

    // ================= PV: 8192 ROI pixels (2048 float4) =================
    float pvsum = 0.f, pvcnt = 0.f;
    {
        const float4* x4 = (const float4*)coord + (size_t)n * 3 * HW4 + half * PV_F4;
        const size_t mbase = (size_t)n * HW4 + (size_t)half * PV_F4;
#pragma unroll 2
        for (int it = 0; it < PV_F4 / BLOCK; ++it) {
            const int f = it * BLOCK + tid;
            float4 X = x4[f], Y = x4[f + HW4], Z = x4[f + 2 * HW4];
            float mv[4];
            if (mode == 0) {
                float4 M = ((const float4*)mask)[mbase + f];
                mv[0] = M.x; mv[1] = M.y; mv[2] = M.z; mv[3] = M.w;
            } else if (mode == 1) {
                int4 M = ((const int4*)mask)[mbase + f];
                mv[0] = (float)M.x; mv[1] = (float)M.y; mv[2] = (float)M.z; mv[3] = (float)M.w;
            } else {
                unsigned w = ((const unsigned*)mask)[mbase + f];
                mv[0] = (float)(w & 255u); mv[1] = (float)((w >> 8) & 255u);
                mv[2] = (float)((w >> 16) & 255u); mv[3] = (float)(w >> 24);
            }
            const float xs[4] = {X.x, X.y, X.z, X.w};
            const float ys[4] = {Y.x, Y.y, Y.z, Y.w};
            const float zs[4] = {Z.x, Z.y, Z.z, Z.w};
#pragma unroll
            for (int k = 0; k < 4; k++) {
                const float v0 = xs[k], v1 = ys[k], v2 = zs[k];
                float p0 = fmaf(Rp[0], v0, fmaf(Rp[1], v1, fmaf(Rp[2], v2, tp0)));
                float p1 = fmaf(Rp[3], v0, fmaf(Rp[4], v1, fmaf(Rp[5], v2, tp1)));
                float p2 = fmaf(Rp[6], v0, fmaf(Rp[7], v1, fmaf(Rp[8], v2, tp2)));
                float g0 = fmaf(Rg[0], v0, fmaf(Rg[1], v1, fmaf(Rg[2], v2, tg0)));
                float g1 = fmaf(Rg[3], v0, fmaf(Rg[4], v1, fmaf(Rg[5], v2, tg1)));
                float g2 = fmaf(Rg[6], v0, fmaf(Rg[7], v1, fmaf(Rg[8], v2, tg2)));
                // p0/p2 - g0/g2 = (p0*g2 - g0*p2)/(p2*g2): one MUFU rcp
                float t0 = fmaf(p0, g2, -(g0 * p2));
                float t1 = fmaf(p1, g2, -(g1 * p2));
                float r  = frcp(p2 * g2);
                float du = fx * (t0 * r);
                float dv = fy * (t1 * r);
                float d  = fsqrt(fmaf(du, du, dv * dv));
                pvsum = fmaf(d, mv[k], pvsum);
                pvcnt += mv[k];
            }
        }
    }

    // ================= MESH: 4096 points =================
    float adsum = 0.f, pjsum = 0.f;
    {
        const int obj = __ldg(obj_id + n);
        const float* mp = mesh + (size_t)obj * MPTS * 3 + (size_t)half * MS_PT * 3;
        float dRl[9];
#pragma unroll
        for (int i = 0; i < 9; i++) dRl[i] = Rp[i] - Rg[i];
        const float dt0 = tp0 - tg0, dt1 = tp1 - tg1, dt2 = tp2 - tg2;
#pragma unroll 4
        for (int it = 0; it < MS_PT / BLOCK; ++it) {
            const int m = it * BLOCK + tid;
            const float v0 = __ldg(mp + m * 3 + 0);
            const float v1 = __ldg(mp + m * 3 + 1);
            const float v2 = __ldg(mp + m * 3 + 2);
            float e0 = fmaf(dRl[0], v0, fmaf(dRl[1], v1, fmaf(dRl[2], v2, dt0)));
            float e1 = fmaf(dRl[3], v0, fmaf(dRl[4], v1, fmaf(dRl[5], v2, dt1)));
            float e2 = fmaf(dRl[6], v0, fmaf(dRl[7], v1, fmaf(dRl[8], v2, dt2)));
            float g0 = fmaf(Rg[0], v0, fmaf(Rg[1], v1, fmaf(Rg[2], v2, tg0)));
            float g1 = fmaf(Rg[3], v0, fmaf(Rg[4], v1, fmaf(Rg[5], v2, tg1)));
            float g2 = fmaf(Rg[6], v0, fmaf(Rg[7], v1, fmaf(Rg[8], v2, tg2)));
            adsum += fsqrt(fmaf(e0, e0, fmaf(e1, e1, e2 * e2)));
            // p = g + e; p0/p2 - g0/g2 = (e0*g2 - g0*e2)/(p2*g2)
            float t0 = fmaf(e0, g2, -(g0 * e2));
            float t1 = fmaf(e1, g2, -(g1 * e2));
            float p2 = g2 + e2;
            float r  = frcp(p2 * g2);
            float du = fx * (t0 * r);
            float dv = fy * (t1 * r);
            pjsum += fsqrt(fmaf(du, du, dv * dv));
        }
    }

    // ---- block reduction (4 warps) ----
#pragma unroll
    for (int o = 16; o; o >>= 1) {
        pvsum += __shfl_down_sync(0xFFFFFFFFu, pvsum, o);
        pvcnt += __shfl_down_sync(0xFFFFFFFFu, pvcnt, o);
        adsum += __shfl_down_sync(0xFFFFFFFFu, adsum, o);
        pjsum += __shfl_down_sync(0xFFFFFFFFu, pjsum, o);
    }
    if (lane == 0) {
        sred[wid][0] = pvsum; sred[wid][1] = pvcnt;
        sred[wid][2] = adsum; sred[wid][3] = pjsum;
    }
    __syncthreads();

    __shared__ bool amSecond;
    if (tid == 0) {
        float s0 = sred[0][0] + sred[1][0] + sred[2][0] + sred[3][0];
        float s1 = sred[0][1] + sred[1][1] + sred[2][1] + sred[3][1];
        float s2 = sred[0][2] + sred[1][2] + sred[2][2] + sred[3][2];
        float s3 = sred[0][3] + sred[1][3] + sred[2][3] + sred[3][3];
        g_part[b] = make_float4(s0, s1, s2, s3);
        __threadfence();
        amSecond = (atomicAdd(&g_flag[n], 1u) == 1u);
    }
    __syncthreads();

    // ---- second finisher for this sample combines halves + writes outputs ----
    if (amSecond && tid == 0) {
        float4 a = __ldcg(&g_part[2 * n]);
        float4 c = __ldcg(&g_part[2 * n + 1]);
        const float pvs = a.x + c.x, pvc = a.y + c.y;
        const float ads = a.z + c.z, pjs = a.w + c.w;
        out[4 * NS + n] = pvs / fmaxf(pvc, 1.0f);
        const int obj = __ldg(obj_id + n);
        out[2 * NS + n] = ads * (1.0f / MPTS) / __ldg(diam + obj);
        out[3 * NS + n] = pjs * (1.0f / MPTS);
        float tr = 0.f;
#pragma unroll
        for (int i = 0; i < 9; i++) tr = fmaf(Rp[i], Rg[i], tr);
        tr = fminf(fmaxf(tr, -1.0f), 3.0f);
        out[n] = acosf((tr - 1.0f) * 0.5f) * 57.29577951308232f;
        const float d0 = tp0 - tg0, d1 = tp1 - tg1, d2 = tp2 - tg2;
        out[NS + n] = sqrtf(fmaf(d0, d0, fmaf(d1, d1, d2 * d2))) * 100.0f;
    }
}

extern "C" void kernel_launch(void* const* d_in, const int* in_sizes, int n_in,
                              void* d_out, int out_size) {
    (void)in_sizes; (void)n_in; (void)out_size;
    const int*   obj_id = (const int*)  d_in[0];
    const float* camK   = (const float*)d_in[1];
    const float* gtR    = (const float*)d_in[2];
    const float* gtT    = (const float*)d_in[3];
    const float* prR    = (const float*)d_in[4];
    const float* prT    = (const float*)d_in[5];
    const float* coord  = (const float*)d_in[6];
    const void*  mask   =               d_in[7];
    const float* mesh   = (const float*)d_in[8];
    const float* diam   = (const float*)d_in[9];
    float* out = (float*)d_out;

    init_kernel<<<1, 32>>>((const unsigned*)mask);
    score_kernel<<<GRID, BLOCK>>>(obj_id, camK, gtR, gtT, prR, prT,
                                  coord, mask, mesh, diam, out);
}